// round 2
// baseline (speedup 1.0000x reference)
#include <cuda_runtime.h>
#include <cstdint>

// ---------------------------------------------------------------------------
// MPS amplitude contraction, segment-table approach.
// amplitude(s) = left[x0] . B[x1] ... B[x62] . right[x63]   (complex, D=16)
//
// Precompute (per launch, tiny cost):
//   Seg3[8]    : products of 3 bulk matrices             (K1, single block)
//   Seg6[64]   : Seg3[a].Seg3[b]                         (K2)
//   Rv3[8]     : B.B.right                               (K1)
//   Lv7[128]   : left[s].Seg6[c]                         (K3)
//   Rv9[512]   : Seg6[c].Rv3[b]                          (K3)
//   Lvec[8192] : Lv7[b].Seg6[c]    (13 bits: x0..x12)    (K4)
//   Rvec[32768]: Seg6[c].Rv9[b]    (15 bits: x49..x63)   (K4)
// Main kernel: per sample = Lvec gather + 6 matvecs vs smem Seg6 + Rvec dot.
// Work per sample drops from 62 matvecs to ~6.2 (10x algebraic reduction).
// ---------------------------------------------------------------------------

__device__ float2 g_seg3[8 * 256];
__device__ float2 g_seg [64 * 256];
__device__ float2 g_rv3 [8 * 16];
__device__ float2 g_lv7 [128 * 16];
__device__ float2 g_rv9 [512 * 16];
__device__ float2 g_lvec[8192 * 16];
__device__ float2 g_rvec[32768 * 16];

// complex fma: (rr,ri) += (ax+i ay) * (bx+i by)
__device__ __forceinline__ void cfma(float& rr, float& ri, float ax, float ay,
                                     float bx, float by) {
    rr = fmaf(ax, bx, rr);
    rr = fmaf(-ay, by, rr);
    ri = fmaf(ax, by, ri);
    ri = fmaf(ay, bx, ri);
}

// ---------------------------------------------------------------------------
// K1: single block. Build Seg3 (levels 1..3) in smem; Rv3 directly.
// ---------------------------------------------------------------------------
__global__ void k1_seed(const float* __restrict__ br_, const float* __restrict__ bi_,
                        const float* __restrict__ rr_, const float* __restrict__ ri_) {
    __shared__ float2 sB [2 * 256];
    __shared__ float2 sL2[4 * 256];
    __shared__ float2 sL3[8 * 256];
    __shared__ float2 sRv[2 * 16];
    int tid = threadIdx.x;

    for (int e = tid; e < 512; e += blockDim.x)
        sB[e] = make_float2(br_[e], bi_[e]);
    for (int e = tid; e < 32; e += blockDim.x)
        sRv[e] = make_float2(rr_[e], ri_[e]);
    __syncthreads();

    // level 2: sL2[b] = sB[b>>1] . sB[b&1]
    for (int e = tid; e < 4 * 256; e += blockDim.x) {
        int b = e >> 8, r = e & 255, i = r >> 4, k = r & 15;
        const float2* O  = sB + ((b >> 1) << 8) + (i << 4);
        const float2* Bm = sB + ((b & 1) << 8);
        float xr = 0.f, xi = 0.f;
#pragma unroll
        for (int j = 0; j < 16; j++) {
            float2 o = O[j], bb = Bm[(j << 4) + k];
            cfma(xr, xi, o.x, o.y, bb.x, bb.y);
        }
        sL2[e] = make_float2(xr, xi);
    }
    __syncthreads();

    // level 3: sL3[b] = sL2[b>>1] . sB[b&1]
    for (int e = tid; e < 8 * 256; e += blockDim.x) {
        int b = e >> 8, r = e & 255, i = r >> 4, k = r & 15;
        const float2* O  = sL2 + ((b >> 1) << 8) + (i << 4);
        const float2* Bm = sB + ((b & 1) << 8);
        float xr = 0.f, xi = 0.f;
#pragma unroll
        for (int j = 0; j < 16; j++) {
            float2 o = O[j], bb = Bm[(j << 4) + k];
            cfma(xr, xi, o.x, o.y, bb.x, bb.y);
        }
        sL3[e] = make_float2(xr, xi);
    }
    __syncthreads();

    for (int e = tid; e < 8 * 256; e += blockDim.x)
        g_seg3[e] = sL3[e];

    // Rv3[v][i] = (B[b2] . B[b1] . right[b0])[i],  v = (b2,b1,b0) MSB..LSB
    if (tid < 128) {
        int v = tid >> 4, i = tid & 15;
        int b2 = (v >> 2) & 1, b1 = (v >> 1) & 1, b0 = v & 1;
        float w1r[16], w1i[16];
#pragma unroll
        for (int a = 0; a < 16; a++) {
            float xr = 0.f, xi = 0.f;
#pragma unroll
            for (int j = 0; j < 16; j++) {
                float2 bb = sB[(b1 << 8) + (a << 4) + j];
                float2 rv = sRv[(b0 << 4) + j];
                cfma(xr, xi, bb.x, bb.y, rv.x, rv.y);
            }
            w1r[a] = xr; w1i[a] = xi;
        }
        float xr = 0.f, xi = 0.f;
#pragma unroll
        for (int j = 0; j < 16; j++) {
            float2 bb = sB[(b2 << 8) + (i << 4) + j];
            cfma(xr, xi, bb.x, bb.y, w1r[j], w1i[j]);
        }
        g_rv3[tid] = make_float2(xr, xi);
    }
}

// ---------------------------------------------------------------------------
// K2: Seg6[(a<<3)|b] = Seg3[a] . Seg3[b]   (16384 threads)
// ---------------------------------------------------------------------------
__global__ void k2_seg6() {
    int t = blockIdx.x * blockDim.x + threadIdx.x;
    if (t >= 64 * 256) return;
    int m = t >> 8, r = t & 255, i = r >> 4, k = r & 15;
    int a = m >> 3, b = m & 7;
    const float2* O  = g_seg3 + (a << 8) + (i << 4);
    const float2* Bm = g_seg3 + (b << 8);
    float xr = 0.f, xi = 0.f;
#pragma unroll
    for (int j = 0; j < 16; j++) {
        float2 o = O[j], bb = Bm[(j << 4) + k];
        cfma(xr, xi, o.x, o.y, bb.x, bb.y);
    }
    g_seg[t] = make_float2(xr, xi);
}

// ---------------------------------------------------------------------------
// K3: Lv7 (128 vecs) and Rv9 (512 vecs).  2048 + 8192 = 10240 threads.
// ---------------------------------------------------------------------------
__global__ void k3_mid(const float* __restrict__ lr_, const float* __restrict__ li_) {
    int t = blockIdx.x * blockDim.x + threadIdx.x;
    if (t < 2048) {
        // Lv7[(s<<6)|c][k] = sum_j left[s][j] * Seg6[c][j][k]
        int v = t >> 4, k = t & 15;
        int s = v >> 6, c = v & 63;
        float xr = 0.f, xi = 0.f;
#pragma unroll
        for (int j = 0; j < 16; j++) {
            float ox = lr_[s * 16 + j], oy = li_[s * 16 + j];
            float2 bb = g_seg[(c << 8) + (j << 4) + k];
            cfma(xr, xi, ox, oy, bb.x, bb.y);
        }
        g_lv7[t] = make_float2(xr, xi);
    } else if (t < 2048 + 8192) {
        // Rv9[(c<<3)|b][i] = sum_j Seg6[c][i][j] * Rv3[b][j]
        int t2 = t - 2048;
        int v = t2 >> 4, i = t2 & 15;
        int c = v >> 3, b = v & 7;
        float xr = 0.f, xi = 0.f;
#pragma unroll
        for (int j = 0; j < 16; j++) {
            float2 bb = g_seg[(c << 8) + (i << 4) + j];
            float2 w  = g_rv3[(b << 4) + j];
            cfma(xr, xi, bb.x, bb.y, w.x, w.y);
        }
        g_rv9[t2] = make_float2(xr, xi);
    }
}

// ---------------------------------------------------------------------------
// K4: Lvec (8192 vecs) and Rvec (32768 vecs). 131072 + 524288 threads.
// ---------------------------------------------------------------------------
__global__ void k4_big() {
    int t = blockIdx.x * blockDim.x + threadIdx.x;
    if (t < 131072) {
        // Lvec[(b7<<6)|c][k] = sum_j Lv7[b7][j] * Seg6[c][j][k]
        int v = t >> 4, k = t & 15;
        int b7 = v >> 6, c = v & 63;
        float xr = 0.f, xi = 0.f;
#pragma unroll
        for (int j = 0; j < 16; j++) {
            float2 o  = g_lv7[(b7 << 4) + j];
            float2 bb = g_seg[(c << 8) + (j << 4) + k];
            cfma(xr, xi, o.x, o.y, bb.x, bb.y);
        }
        g_lvec[t] = make_float2(xr, xi);
    } else if (t < 131072 + 524288) {
        // Rvec[(c<<9)|b][i] = sum_j Seg6[c][i][j] * Rv9[b][j]
        int t2 = t - 131072;
        int v = t2 >> 4, i = t2 & 15;
        int c = v >> 9, b = v & 511;
        float xr = 0.f, xi = 0.f;
#pragma unroll
        for (int j = 0; j < 16; j++) {
            float2 bb = g_seg[(c << 8) + (i << 4) + j];
            float2 w  = g_rv9[(b << 4) + j];
            cfma(xr, xi, bb.x, bb.y, w.x, w.y);
        }
        g_rvec[t2] = make_float2(xr, xi);
    }
}

// ---------------------------------------------------------------------------
// Main kernel. One thread per sample (grid-stride). Seg6 table in smem,
// XOR-swizzled: element (idx,i,j) stored at idx*256 + i*16 + (j ^ (idx&15)).
// A warp's 32 lanes generally hold distinct idx; the swizzle spreads their
// row reads across all 32 banks.
// ---------------------------------------------------------------------------
__global__ __launch_bounds__(512) void k_main(const int* __restrict__ x,
                                              float* __restrict__ out, int N) {
    extern __shared__ float2 sSeg[];  // 64 * 256 float2 = 128 KB

    for (int e = threadIdx.x; e < 64 * 256; e += blockDim.x) {
        int idx = e >> 8, r = e & 255, i = r >> 4, j = r & 15;
        sSeg[(idx << 8) + (i << 4) + (j ^ (idx & 15))] = g_seg[e];
    }
    __syncthreads();

    int stride = gridDim.x * blockDim.x;
    for (int s = blockIdx.x * blockDim.x + threadIdx.x; s < N; s += stride) {
        // ---- gather 64 spin bits (16 x int4 loads), pack into 3 fields ----
        const int4* xr = reinterpret_cast<const int4*>(x) + ((size_t)s << 4);
        unsigned w[16];
#pragma unroll
        for (int q = 0; q < 16; q++) {
            int4 v = __ldg(xr + q);
            w[q] = ((unsigned)(v.x & 1) << 3) | ((unsigned)(v.y & 1) << 2) |
                   ((unsigned)(v.z & 1) << 1) |  (unsigned)(v.w & 1);
        }
        // bits t = 4q..4q+3 live in w[q] (MSB-first within the nibble)
        unsigned idxl = (w[0] << 9) | (w[1] << 5) | (w[2] << 1) | (w[3] >> 3);   // x0..x12
        unsigned long long segp =                                               // x13..x48
            ((unsigned long long)(w[3] & 7ull) << 33) |
            ((unsigned long long)w[4] << 29) | ((unsigned long long)w[5] << 25) |
            ((unsigned long long)w[6] << 21) | ((unsigned long long)w[7] << 17) |
            ((unsigned long long)w[8] << 13) | ((unsigned long long)w[9] << 9)  |
            ((unsigned long long)w[10] << 5) | ((unsigned long long)w[11] << 1) |
            ((unsigned long long)(w[12] >> 3));
        unsigned idxr = ((w[12] & 7u) << 12) | (w[13] << 8) | (w[14] << 4) | w[15]; // x49..x63

        // ---- start vector: Lvec[idxl] ----
        float mr[16], mi[16];
        const float4* lv = reinterpret_cast<const float4*>(g_lvec + ((size_t)idxl << 4));
#pragma unroll
        for (int q = 0; q < 8; q++) {
            float4 v = __ldg(lv + q);
            mr[2 * q]     = v.x; mi[2 * q]     = v.y;
            mr[2 * q + 1] = v.z; mi[2 * q + 1] = v.w;
        }

        // ---- 6 segment matvecs: m <- m . Seg6[idx] ----
#pragma unroll 1
        for (int kseg = 0; kseg < 6; kseg++) {
            unsigned idx = (unsigned)(segp >> 30) & 63u;
            segp <<= 6;
            const float2* M = sSeg + (idx << 8);
            unsigned xo = idx & 15u;
            float nr[16], ni[16];
#pragma unroll
            for (int j = 0; j < 16; j++) { nr[j] = 0.f; ni[j] = 0.f; }
#pragma unroll
            for (int i = 0; i < 16; i++) {
                float ar = mr[i], ai = mi[i];
                const float2* Mi = M + (i << 4);
#pragma unroll
                for (int j = 0; j < 16; j++) {
                    float2 b = Mi[j ^ xo];
                    nr[j] = fmaf(ar, b.x, nr[j]);
                    nr[j] = fmaf(-ai, b.y, nr[j]);
                    ni[j] = fmaf(ar, b.y, ni[j]);
                    ni[j] = fmaf(ai, b.x, ni[j]);
                }
            }
#pragma unroll
            for (int j = 0; j < 16; j++) { mr[j] = nr[j]; mi[j] = ni[j]; }
        }

        // ---- final dot with Rvec[idxr] ----
        const float4* rv = reinterpret_cast<const float4*>(g_rvec + ((size_t)idxr << 4));
        float ar = 0.f, ai = 0.f;
#pragma unroll
        for (int q = 0; q < 8; q++) {
            float4 v = __ldg(rv + q);
            ar = fmaf(mr[2 * q], v.x, ar);      ar = fmaf(-mi[2 * q], v.y, ar);
            ai = fmaf(mr[2 * q], v.y, ai);      ai = fmaf(mi[2 * q], v.x, ai);
            ar = fmaf(mr[2 * q + 1], v.z, ar);  ar = fmaf(-mi[2 * q + 1], v.w, ar);
            ai = fmaf(mr[2 * q + 1], v.w, ai);  ai = fmaf(mi[2 * q + 1], v.z, ai);
        }

        out[s]     = ar;
        out[N + s] = ai;
    }
}

// ---------------------------------------------------------------------------
// kernel_launch
// inputs (metadata order): x, left_r, left_i, bulk_r, bulk_i, right_r, right_i
// out: float32, [2, N] flattened (re then im)
// ---------------------------------------------------------------------------
extern "C" void kernel_launch(void* const* d_in, const int* in_sizes, int n_in,
                              void* d_out, int out_size) {
    const int*   x       = (const int*)d_in[0];
    const float* left_r  = (const float*)d_in[1];
    const float* left_i  = (const float*)d_in[2];
    const float* bulk_r  = (const float*)d_in[3];
    const float* bulk_i  = (const float*)d_in[4];
    const float* right_r = (const float*)d_in[5];
    const float* right_i = (const float*)d_in[6];
    float* out = (float*)d_out;

    int N = in_sizes[0] / 64;

    static const size_t kSmem = 64 * 256 * sizeof(float2);  // 128 KB
    cudaFuncSetAttribute(k_main, cudaFuncAttributeMaxDynamicSharedMemorySize,
                         (int)kSmem);

    k1_seed<<<1, 512>>>(bulk_r, bulk_i, right_r, right_i);
    k2_seg6<<<64, 256>>>();
    k3_mid<<<40, 256>>>(left_r, left_i);
    k4_big<<<2560, 256>>>();
    k_main<<<148, 512, kSmem>>>(x, out, N);
}

// round 3
// speedup vs baseline: 1.7932x; 1.7932x over previous
#include <cuda_runtime.h>
#include <cstdint>

// ---------------------------------------------------------------------------
// MPS amplitude contraction, segment-table approach (v3).
// amplitude(s) = left[x0] . B[x1] ... B[x62] . right[x63]   (complex, D=16)
//
// Split: Lvec covers x0..x13 (14 bits), 6 x Seg6 cover x14..x49 (36 bits),
//        Rvec covers x50..x63 (14 bits).
// Main kernel per sample: Lvec gather + 6 smem matvecs + Rvec dot, with
// lane-rotated column order (deterministic 4-phase LDS.128, idx-independent)
// and packed fma.rn.f32x2 dual-accumulator complex arithmetic.
// ---------------------------------------------------------------------------

typedef unsigned long long ull;

__device__ float2 g_seg3[8 * 256];
__device__ float2 g_seg [64 * 256];
__device__ float2 g_lv2 [4 * 16];
__device__ float2 g_rv2 [4 * 16];
__device__ float2 g_lv8 [256 * 16];
__device__ float2 g_rv8 [256 * 16];
__device__ float2 g_lvec[16384 * 16];
__device__ float2 g_rvec[16384 * 16];

// ---- packed fp32x2 helpers ----
__device__ __forceinline__ ull pack2(float lo, float hi) {
    ull r; asm("mov.b64 %0, {%1,%2};" : "=l"(r) : "f"(lo), "f"(hi)); return r;
}
__device__ __forceinline__ void unpack2(ull v, float& lo, float& hi) {
    asm("mov.b64 {%0,%1}, %2;" : "=f"(lo), "=f"(hi) : "l"(v));
}
__device__ __forceinline__ ull ffma2(ull a, ull b, ull c) {
    ull d; asm("fma.rn.f32x2 %0, %1, %2, %3;" : "=l"(d) : "l"(a), "l"(b), "l"(c));
    return d;
}
__device__ __forceinline__ void lds128(unsigned addr, ull& p0, ull& p1) {
    asm volatile("ld.shared.v2.b64 {%0,%1}, [%2];" : "=l"(p0), "=l"(p1) : "r"(addr));
}
__device__ __forceinline__ void ldg128(const void* p, ull& p0, ull& p1) {
    asm volatile("ld.global.nc.v2.b64 {%0,%1}, [%2];" : "=l"(p0), "=l"(p1) : "l"(p));
}

// scalar complex fma: (rr,ri) += (ax+i ay) * (bx+i by)
__device__ __forceinline__ void cfma(float& rr, float& ri, float ax, float ay,
                                     float bx, float by) {
    rr = fmaf(ax, bx, rr);
    rr = fmaf(-ay, by, rr);
    ri = fmaf(ax, by, ri);
    ri = fmaf(ay, bx, ri);
}

// ---------------------------------------------------------------------------
// K1: single block. Seg3 (levels 1..3), Lv2 = left.B, Rv2 = B.right.
// ---------------------------------------------------------------------------
__global__ void k1_seed(const float* __restrict__ br_, const float* __restrict__ bi_,
                        const float* __restrict__ lr_, const float* __restrict__ li_,
                        const float* __restrict__ rr_, const float* __restrict__ ri_) {
    __shared__ float2 sB [2 * 256];
    __shared__ float2 sL2[4 * 256];
    int tid = threadIdx.x;

    for (int e = tid; e < 512; e += blockDim.x)
        sB[e] = make_float2(br_[e], bi_[e]);
    __syncthreads();

    // level 2: sL2[b] = sB[b>>1] . sB[b&1]
    for (int e = tid; e < 4 * 256; e += blockDim.x) {
        int b = e >> 8, r = e & 255, i = r >> 4, k = r & 15;
        const float2* O  = sB + ((b >> 1) << 8) + (i << 4);
        const float2* Bm = sB + ((b & 1) << 8);
        float xr = 0.f, xi = 0.f;
#pragma unroll
        for (int j = 0; j < 16; j++) {
            float2 o = O[j], bb = Bm[(j << 4) + k];
            cfma(xr, xi, o.x, o.y, bb.x, bb.y);
        }
        sL2[e] = make_float2(xr, xi);
    }
    __syncthreads();

    // level 3: g_seg3[b] = sL2[b>>1] . sB[b&1]   (MSB-first bit order)
    for (int e = tid; e < 8 * 256; e += blockDim.x) {
        int b = e >> 8, r = e & 255, i = r >> 4, k = r & 15;
        const float2* O  = sL2 + ((b >> 1) << 8) + (i << 4);
        const float2* Bm = sB + ((b & 1) << 8);
        float xr = 0.f, xi = 0.f;
#pragma unroll
        for (int j = 0; j < 16; j++) {
            float2 o = O[j], bb = Bm[(j << 4) + k];
            cfma(xr, xi, o.x, o.y, bb.x, bb.y);
        }
        g_seg3[e] = make_float2(xr, xi);
    }

    // Lv2[(s<<1)|b][k] = sum_j left[s][j] * B[b][j][k]
    if (tid < 64) {
        int v = tid >> 4, k = tid & 15;
        int s = v >> 1, b = v & 1;
        float xr = 0.f, xi = 0.f;
#pragma unroll
        for (int j = 0; j < 16; j++) {
            float2 bb = sB[(b << 8) + (j << 4) + k];
            cfma(xr, xi, lr_[s * 16 + j], li_[s * 16 + j], bb.x, bb.y);
        }
        g_lv2[tid] = make_float2(xr, xi);
    }
    // Rv2[(b<<1)|r][i] = sum_j B[b][i][j] * right[r][j]
    if (tid >= 64 && tid < 128) {
        int t2 = tid - 64;
        int v = t2 >> 4, i = t2 & 15;
        int b = v >> 1, r = v & 1;
        float xr = 0.f, xi = 0.f;
#pragma unroll
        for (int j = 0; j < 16; j++) {
            float2 bb = sB[(b << 8) + (i << 4) + j];
            cfma(xr, xi, bb.x, bb.y, rr_[r * 16 + j], ri_[r * 16 + j]);
        }
        g_rv2[t2] = make_float2(xr, xi);
    }
}

// ---------------------------------------------------------------------------
// K2: Seg6[(a<<3)|b] = Seg3[a] . Seg3[b]   (16384 threads)
// ---------------------------------------------------------------------------
__global__ void k2_seg6() {
    int t = blockIdx.x * blockDim.x + threadIdx.x;
    if (t >= 64 * 256) return;
    int m = t >> 8, r = t & 255, i = r >> 4, k = r & 15;
    int a = m >> 3, b = m & 7;
    const float2* O  = g_seg3 + (a << 8) + (i << 4);
    const float2* Bm = g_seg3 + (b << 8);
    float xr = 0.f, xi = 0.f;
#pragma unroll
    for (int j = 0; j < 16; j++) {
        float2 o = O[j], bb = Bm[(j << 4) + k];
        cfma(xr, xi, o.x, o.y, bb.x, bb.y);
    }
    g_seg[t] = make_float2(xr, xi);
}

// ---------------------------------------------------------------------------
// K3: Lv8[(a2<<6)|c] = Lv2[a2].Seg6[c];  Rv8[(c<<2)|b2] = Seg6[c].Rv2[b2]
// 4096 + 4096 threads.
// ---------------------------------------------------------------------------
__global__ void k3_mid() {
    int t = blockIdx.x * blockDim.x + threadIdx.x;
    if (t < 4096) {
        int v = t >> 4, k = t & 15;
        int a2 = v >> 6, c = v & 63;
        float xr = 0.f, xi = 0.f;
#pragma unroll
        for (int j = 0; j < 16; j++) {
            float2 o  = g_lv2[(a2 << 4) + j];
            float2 bb = g_seg[(c << 8) + (j << 4) + k];
            cfma(xr, xi, o.x, o.y, bb.x, bb.y);
        }
        g_lv8[t] = make_float2(xr, xi);
    } else if (t < 8192) {
        int t2 = t - 4096;
        int v = t2 >> 4, i = t2 & 15;
        int c = v >> 2, b2 = v & 3;
        float xr = 0.f, xi = 0.f;
#pragma unroll
        for (int j = 0; j < 16; j++) {
            float2 bb = g_seg[(c << 8) + (i << 4) + j];
            float2 w  = g_rv2[(b2 << 4) + j];
            cfma(xr, xi, bb.x, bb.y, w.x, w.y);
        }
        g_rv8[t2] = make_float2(xr, xi);
    }
}

// ---------------------------------------------------------------------------
// K4: Lvec[(a8<<6)|c] = Lv8[a8].Seg6[c];  Rvec[(c<<8)|b8] = Seg6[c].Rv8[b8]
// 262144 + 262144 threads.
// ---------------------------------------------------------------------------
__global__ void k4_big() {
    int t = blockIdx.x * blockDim.x + threadIdx.x;
    if (t < 262144) {
        int v = t >> 4, k = t & 15;
        int a8 = v >> 6, c = v & 63;
        float xr = 0.f, xi = 0.f;
#pragma unroll
        for (int j = 0; j < 16; j++) {
            float2 o  = g_lv8[(a8 << 4) + j];
            float2 bb = g_seg[(c << 8) + (j << 4) + k];
            cfma(xr, xi, o.x, o.y, bb.x, bb.y);
        }
        g_lvec[t] = make_float2(xr, xi);
    } else if (t < 524288) {
        int t2 = t - 262144;
        int v = t2 >> 4, i = t2 & 15;
        int c = v >> 8, b8 = v & 255;
        float xr = 0.f, xi = 0.f;
#pragma unroll
        for (int j = 0; j < 16; j++) {
            float2 bb = g_seg[(c << 8) + (i << 4) + j];
            float2 w  = g_rv8[(b8 << 4) + j];
            cfma(xr, xi, bb.x, bb.y, w.x, w.y);
        }
        g_rvec[t2] = make_float2(xr, xi);
    }
}

// ---------------------------------------------------------------------------
// Main kernel. One thread per sample. Table (128 KB) in smem, PLAIN layout.
// Column pairs are read in lane-rotated order p = (u + lane&7)&7 so each
// LDS.128 is a deterministic 4-phase (512B) access regardless of idx.
// Register pair u of the state vector holds LOGICAL element pair (u+rot)&7.
// ---------------------------------------------------------------------------
__global__ __launch_bounds__(512) void k_main(const int* __restrict__ x,
                                              float* __restrict__ out, int N) {
    extern __shared__ float2 sSeg[];  // 64 * 256 float2 = 128 KB, plain layout

    {
        const float4* src = reinterpret_cast<const float4*>(g_seg);
        float4* dst = reinterpret_cast<float4*>(sSeg);
        for (int e = threadIdx.x; e < 64 * 128; e += blockDim.x) dst[e] = src[e];
    }
    __syncthreads();

    unsigned sb;
    asm("{ .reg .u64 t; cvta.to.shared.u64 t, %1; cvt.u32.u64 %0, t; }"
        : "=r"(sb) : "l"(sSeg));
    const unsigned rot   = threadIdx.x & 7u;
    const unsigned rot16 = rot << 4;
    const unsigned rot256 = rot << 8;

    int stride = gridDim.x * blockDim.x;
    for (int s = blockIdx.x * blockDim.x + threadIdx.x; s < N; s += stride) {
        // ---- gather 64 spin bits (16 x int4), pack MSB-first ----
        const int4* xr = reinterpret_cast<const int4*>(x) + ((size_t)s << 4);
        unsigned w[16];
#pragma unroll
        for (int q = 0; q < 16; q++) {
            int4 v = __ldg(xr + q);
            w[q] = ((unsigned)(v.x & 1) << 3) | ((unsigned)(v.y & 1) << 2) |
                   ((unsigned)(v.z & 1) << 1) |  (unsigned)(v.w & 1);
        }
        unsigned idxl = (w[0] << 10) | (w[1] << 6) | (w[2] << 2) | (w[3] >> 2);  // x0..x13
        ull segp =                                                               // x14..x49
            ((ull)(w[3] & 3u) << 34) |
            ((ull)w[4]  << 30) | ((ull)w[5]  << 26) | ((ull)w[6] << 22) |
            ((ull)w[7]  << 18) | ((ull)w[8]  << 14) | ((ull)w[9] << 10) |
            ((ull)w[10] << 6)  | ((ull)w[11] << 2)  | ((ull)(w[12] >> 2));
        unsigned idxr = ((w[12] & 3u) << 12) | (w[13] << 8) | (w[14] << 4) | w[15]; // x50..x63

        // ---- start vector: Lvec[idxl], LOGICAL register order ----
        float mr[16], mi[16];
        {
            const char* lb = (const char*)g_lvec + ((size_t)idxl << 7);
#pragma unroll
            for (int u = 0; u < 8; u++) {
                ull a, b;
                ldg128(lb + (u << 4), a, b);
                unpack2(a, mr[2 * u],     mi[2 * u]);
                unpack2(b, mr[2 * u + 1], mi[2 * u + 1]);
            }
        }

        // ---- matvec 1: m is in logical order (rows by immediate offset) ----
        {
            unsigned idx = (unsigned)(segp >> 30) & 63u;
            segp <<= 6;
            unsigned mb = sb + (idx << 11);
            ull P[16], Q[16];
#pragma unroll
            for (int e = 0; e < 16; e++) { P[e] = 0ull; Q[e] = 0ull; }
            unsigned pu[8];
#pragma unroll
            for (int u = 0; u < 8; u++) pu[u] = mb + ((rot16 + (u << 4)) & 127u);
#pragma unroll
            for (int i = 0; i < 16; i++) {
                float ar = mr[i], ai = mi[i];
                ull arr = pack2(ar, ar), ai2 = pack2(ai, -ai);
#pragma unroll
                for (int u = 0; u < 8; u++) {
                    ull b0, b1;
                    lds128(pu[u] + (unsigned)(i << 7), b0, b1);
                    P[2 * u]     = ffma2(arr, b0, P[2 * u]);
                    Q[2 * u]     = ffma2(ai2, b0, Q[2 * u]);
                    P[2 * u + 1] = ffma2(arr, b1, P[2 * u + 1]);
                    Q[2 * u + 1] = ffma2(ai2, b1, Q[2 * u + 1]);
                }
            }
#pragma unroll
            for (int e = 0; e < 16; e++) {
                float pl, ph, ql, qh;
                unpack2(P[e], pl, ph);
                unpack2(Q[e], ql, qh);
                mr[e] = pl + qh;   // nr = ar*bx - ai*by
                mi[e] = ph + ql;   // ni = ar*by + ai*bx
            }
        }

        // ---- matvecs 2..6: m register pair sp holds logical pair (sp+rot)&7 ----
#pragma unroll 1
        for (int kseg = 1; kseg < 6; kseg++) {
            unsigned idx = (unsigned)(segp >> 30) & 63u;
            segp <<= 6;
            unsigned mb = sb + (idx << 11);
            ull P[16], Q[16];
#pragma unroll
            for (int e = 0; e < 16; e++) { P[e] = 0ull; Q[e] = 0ull; }
            unsigned pu[8];
#pragma unroll
            for (int u = 0; u < 8; u++) pu[u] = mb + ((rot16 + (u << 4)) & 127u);
#pragma unroll
            for (int sp = 0; sp < 8; sp++) {
                unsigned row = (rot256 + (unsigned)(sp << 8)) & 2047u;
#pragma unroll
                for (int hf = 0; hf < 2; hf++) {
                    float ar = mr[2 * sp + hf], ai = mi[2 * sp + hf];
                    ull arr = pack2(ar, ar), ai2 = pack2(ai, -ai);
#pragma unroll
                    for (int u = 0; u < 8; u++) {
                        ull b0, b1;
                        lds128(pu[u] + row + (unsigned)(hf << 7), b0, b1);
                        P[2 * u]     = ffma2(arr, b0, P[2 * u]);
                        Q[2 * u]     = ffma2(ai2, b0, Q[2 * u]);
                        P[2 * u + 1] = ffma2(arr, b1, P[2 * u + 1]);
                        Q[2 * u + 1] = ffma2(ai2, b1, Q[2 * u + 1]);
                    }
                }
            }
#pragma unroll
            for (int e = 0; e < 16; e++) {
                float pl, ph, ql, qh;
                unpack2(P[e], pl, ph);
                unpack2(Q[e], ql, qh);
                mr[e] = pl + qh;
                mi[e] = ph + ql;
            }
        }

        // ---- final dot with Rvec[idxr], same pair rotation ----
        float accr = 0.f, acci = 0.f;
        {
            const char* rb = (const char*)g_rvec + ((size_t)idxr << 7);
#pragma unroll
            for (int u = 0; u < 8; u++) {
                ull a, b;
                ldg128(rb + ((rot16 + (u << 4)) & 127u), a, b);
                float c0x, c0y, c1x, c1y;
                unpack2(a, c0x, c0y);
                unpack2(b, c1x, c1y);
                int e0 = 2 * u, e1 = 2 * u + 1;
                accr = fmaf(mr[e0], c0x, accr);  accr = fmaf(-mi[e0], c0y, accr);
                acci = fmaf(mr[e0], c0y, acci);  acci = fmaf(mi[e0], c0x, acci);
                accr = fmaf(mr[e1], c1x, accr);  accr = fmaf(-mi[e1], c1y, accr);
                acci = fmaf(mr[e1], c1y, acci);  acci = fmaf(mi[e1], c1x, acci);
            }
        }

        out[s]     = accr;
        out[N + s] = acci;
    }
}

// ---------------------------------------------------------------------------
// kernel_launch
// inputs (metadata order): x, left_r, left_i, bulk_r, bulk_i, right_r, right_i
// out: float32, [2, N] flattened (re then im)
// ---------------------------------------------------------------------------
extern "C" void kernel_launch(void* const* d_in, const int* in_sizes, int n_in,
                              void* d_out, int out_size) {
    const int*   x       = (const int*)d_in[0];
    const float* left_r  = (const float*)d_in[1];
    const float* left_i  = (const float*)d_in[2];
    const float* bulk_r  = (const float*)d_in[3];
    const float* bulk_i  = (const float*)d_in[4];
    const float* right_r = (const float*)d_in[5];
    const float* right_i = (const float*)d_in[6];
    float* out = (float*)d_out;

    int N = in_sizes[0] / 64;

    static const size_t kSmem = 64 * 256 * sizeof(float2);  // 128 KB
    cudaFuncSetAttribute(k_main, cudaFuncAttributeMaxDynamicSharedMemorySize,
                         (int)kSmem);

    k1_seed<<<1, 512>>>(bulk_r, bulk_i, left_r, left_i, right_r, right_i);
    k2_seg6<<<64, 256>>>();
    k3_mid<<<32, 256>>>();
    k4_big<<<2048, 256>>>();
    k_main<<<148, 512, kSmem>>>(x, out, N);
}

// round 5
// speedup vs baseline: 2.1087x; 1.1760x over previous
#include <cuda_runtime.h>
#include <cstdint>

// ---------------------------------------------------------------------------
// MPS amplitude contraction, segment-table approach (v5 = v4 + k0 grid fix).
// amplitude(s) = left[x0] . B[x1] ... B[x62] . right[x63]   (complex, D=16)
//
// Split: Lvec covers x0..x13 (14 bits), 6 x Seg6 cover x14..x49 (36 bits),
//        Rvec covers x50..x63 (14 bits).
// ---------------------------------------------------------------------------

typedef unsigned long long ull;

__device__ float2 g_seg3[8 * 256];
__device__ float2 g_seg [64 * 256];
__device__ float2 g_lv2 [4 * 16];
__device__ float2 g_rv2 [4 * 16];
__device__ float2 g_lv8 [256 * 16];
__device__ float2 g_rv8 [256 * 16];
__device__ float2 g_lvec[16384 * 16];
__device__ float2 g_rvec[16384 * 16];
__device__ ull    g_xpack[131072];

// ---- packed fp32x2 helpers ----
__device__ __forceinline__ ull pack2(float lo, float hi) {
    ull r; asm("mov.b64 %0, {%1,%2};" : "=l"(r) : "f"(lo), "f"(hi)); return r;
}
__device__ __forceinline__ void unpack2(ull v, float& lo, float& hi) {
    asm("mov.b64 {%0,%1}, %2;" : "=f"(lo), "=f"(hi) : "l"(v));
}
__device__ __forceinline__ ull ffma2(ull a, ull b, ull c) {
    ull d; asm("fma.rn.f32x2 %0, %1, %2, %3;" : "=l"(d) : "l"(a), "l"(b), "l"(c));
    return d;
}
__device__ __forceinline__ void lds128(unsigned addr, ull& p0, ull& p1) {
    asm volatile("ld.shared.v2.b64 {%0,%1}, [%2];" : "=l"(p0), "=l"(p1) : "r"(addr));
}
__device__ __forceinline__ void ldg128(const void* p, ull& p0, ull& p1) {
    asm volatile("ld.global.nc.v2.b64 {%0,%1}, [%2];" : "=l"(p0), "=l"(p1) : "l"(p));
}

// scalar complex fma: (rr,ri) += (ax+i ay) * (bx+i by)
__device__ __forceinline__ void cfma(float& rr, float& ri, float ax, float ay,
                                     float bx, float by) {
    rr = fmaf(ax, bx, rr);
    rr = fmaf(-ay, by, rr);
    ri = fmaf(ax, by, ri);
    ri = fmaf(ay, bx, ri);
}

// ---------------------------------------------------------------------------
// K0: pack spin bits. Warp W packs samples [32W, 32W+32): two coalesced
// 32-int loads + ballots per sample; packed bit (63-t) = x_t (MSB-first).
// Launch with N/256 blocks of 256 threads (8 warps x 32 samples = 256/block).
// ---------------------------------------------------------------------------
__global__ void k0_pack(const int* __restrict__ x, int N) {
    int W = (blockIdx.x * blockDim.x + threadIdx.x) >> 5;
    int lane = threadIdx.x & 31;
    int s0 = W << 5;
    if (s0 >= N) return;
    ull mine = 0;
#pragma unroll 1
    for (int q = 0; q < 32; q++) {
        size_t base = (size_t)(s0 + q) << 6;
        unsigned b0 = __ballot_sync(0xFFFFFFFFu, x[base + lane] & 1);
        unsigned b1 = __ballot_sync(0xFFFFFFFFu, x[base + 32 + lane] & 1);
        ull packed = ((ull)__brev(b0) << 32) | (ull)__brev(b1);
        if (lane == q) mine = packed;
    }
    g_xpack[s0 + lane] = mine;
}

// ---------------------------------------------------------------------------
// K1: single block. Seg3 (levels 1..3), Lv2 = left.B, Rv2 = B.right.
// ---------------------------------------------------------------------------
__global__ void k1_seed(const float* __restrict__ br_, const float* __restrict__ bi_,
                        const float* __restrict__ lr_, const float* __restrict__ li_,
                        const float* __restrict__ rr_, const float* __restrict__ ri_) {
    __shared__ float2 sB [2 * 256];
    __shared__ float2 sL2[4 * 256];
    int tid = threadIdx.x;

    for (int e = tid; e < 512; e += blockDim.x)
        sB[e] = make_float2(br_[e], bi_[e]);
    __syncthreads();

    for (int e = tid; e < 4 * 256; e += blockDim.x) {
        int b = e >> 8, r = e & 255, i = r >> 4, k = r & 15;
        const float2* O  = sB + ((b >> 1) << 8) + (i << 4);
        const float2* Bm = sB + ((b & 1) << 8);
        float xr = 0.f, xi = 0.f;
#pragma unroll
        for (int j = 0; j < 16; j++) {
            float2 o = O[j], bb = Bm[(j << 4) + k];
            cfma(xr, xi, o.x, o.y, bb.x, bb.y);
        }
        sL2[e] = make_float2(xr, xi);
    }
    __syncthreads();

    for (int e = tid; e < 8 * 256; e += blockDim.x) {
        int b = e >> 8, r = e & 255, i = r >> 4, k = r & 15;
        const float2* O  = sL2 + ((b >> 1) << 8) + (i << 4);
        const float2* Bm = sB + ((b & 1) << 8);
        float xr = 0.f, xi = 0.f;
#pragma unroll
        for (int j = 0; j < 16; j++) {
            float2 o = O[j], bb = Bm[(j << 4) + k];
            cfma(xr, xi, o.x, o.y, bb.x, bb.y);
        }
        g_seg3[e] = make_float2(xr, xi);
    }

    if (tid < 64) {  // Lv2[(s<<1)|b][k] = sum_j left[s][j] * B[b][j][k]
        int v = tid >> 4, k = tid & 15;
        int s = v >> 1, b = v & 1;
        float xr = 0.f, xi = 0.f;
#pragma unroll
        for (int j = 0; j < 16; j++) {
            float2 bb = sB[(b << 8) + (j << 4) + k];
            cfma(xr, xi, lr_[s * 16 + j], li_[s * 16 + j], bb.x, bb.y);
        }
        g_lv2[tid] = make_float2(xr, xi);
    }
    if (tid >= 64 && tid < 128) {  // Rv2[(b<<1)|r][i] = sum_j B[b][i][j]*right[r][j]
        int t2 = tid - 64;
        int v = t2 >> 4, i = t2 & 15;
        int b = v >> 1, r = v & 1;
        float xr = 0.f, xi = 0.f;
#pragma unroll
        for (int j = 0; j < 16; j++) {
            float2 bb = sB[(b << 8) + (i << 4) + j];
            cfma(xr, xi, bb.x, bb.y, rr_[r * 16 + j], ri_[r * 16 + j]);
        }
        g_rv2[t2] = make_float2(xr, xi);
    }
}

// ---------------------------------------------------------------------------
// K2: Seg6[(a<<3)|b] = Seg3[a] . Seg3[b]
// ---------------------------------------------------------------------------
__global__ void k2_seg6() {
    int t = blockIdx.x * blockDim.x + threadIdx.x;
    if (t >= 64 * 256) return;
    int m = t >> 8, r = t & 255, i = r >> 4, k = r & 15;
    int a = m >> 3, b = m & 7;
    const float2* O  = g_seg3 + (a << 8) + (i << 4);
    const float2* Bm = g_seg3 + (b << 8);
    float xr = 0.f, xi = 0.f;
#pragma unroll
    for (int j = 0; j < 16; j++) {
        float2 o = O[j], bb = Bm[(j << 4) + k];
        cfma(xr, xi, o.x, o.y, bb.x, bb.y);
    }
    g_seg[t] = make_float2(xr, xi);
}

// ---------------------------------------------------------------------------
// K3: Lv8[(a2<<6)|c] = Lv2[a2].Seg6[c];  Rv8[(c<<2)|b2] = Seg6[c].Rv2[b2]
// ---------------------------------------------------------------------------
__global__ void k3_mid() {
    int t = blockIdx.x * blockDim.x + threadIdx.x;
    if (t < 4096) {
        int v = t >> 4, k = t & 15;
        int a2 = v >> 6, c = v & 63;
        float xr = 0.f, xi = 0.f;
#pragma unroll
        for (int j = 0; j < 16; j++) {
            float2 o  = g_lv2[(a2 << 4) + j];
            float2 bb = g_seg[(c << 8) + (j << 4) + k];
            cfma(xr, xi, o.x, o.y, bb.x, bb.y);
        }
        g_lv8[t] = make_float2(xr, xi);
    } else if (t < 8192) {
        int t2 = t - 4096;
        int v = t2 >> 4, i = t2 & 15;
        int c = v >> 2, b2 = v & 3;
        float xr = 0.f, xi = 0.f;
#pragma unroll
        for (int j = 0; j < 16; j++) {
            float2 bb = g_seg[(c << 8) + (i << 4) + j];
            float2 w  = g_rv2[(b2 << 4) + j];
            cfma(xr, xi, bb.x, bb.y, w.x, w.y);
        }
        g_rv8[t2] = make_float2(xr, xi);
    }
}

// ---------------------------------------------------------------------------
// K4: one block per (side, c).  Seg6[c] staged in smem (transposed for the
// Rvec side); per-output 16-vector comes via broadcast __ldg.
// Blocks 0..63: Lvec[(a8<<6)|c] = Lv8[a8].Seg6[c]
// Blocks 64..127: Rvec[(c<<8)|b8] = Seg6[c].Rv8[b8]
// ---------------------------------------------------------------------------
__global__ void k4_big() {
    __shared__ float2 S[256];
    int blk = blockIdx.x;
    int t = threadIdx.x;
    if (blk < 64) {
        int c = blk;
        S[t] = g_seg[(c << 8) + t];           // S[j*16+k] = Seg6[c][j][k]
        __syncthreads();
        int k = t & 15, a8l = t >> 4;
#pragma unroll 1
        for (int p = 0; p < 16; p++) {
            int a8 = (p << 4) | a8l;
            const float2* w = g_lv8 + (a8 << 4);
            float xr = 0.f, xi = 0.f;
#pragma unroll
            for (int j = 0; j < 16; j++) {
                float2 o = __ldg(&w[j]);       // warp-broadcast
                float2 bb = S[(j << 4) + k];   // conflict-free
                cfma(xr, xi, o.x, o.y, bb.x, bb.y);
            }
            g_lvec[(((a8 << 6) | c) << 4) + k] = make_float2(xr, xi);
        }
    } else {
        int c = blk - 64;
        {
            int i = t >> 4, j = t & 15;
            S[(j << 4) | i] = g_seg[(c << 8) + t];  // transposed stage
        }
        __syncthreads();
        int il = t & 15, b8l = t >> 4;
#pragma unroll 1
        for (int p = 0; p < 16; p++) {
            int b8 = (p << 4) | b8l;
            const float2* w = g_rv8 + (b8 << 4);
            float xr = 0.f, xi = 0.f;
#pragma unroll
            for (int j = 0; j < 16; j++) {
                float2 ww = __ldg(&w[j]);      // warp-broadcast
                float2 bb = S[(j << 4) + il];  // Seg6[c][il][j]
                cfma(xr, xi, bb.x, bb.y, ww.x, ww.y);
            }
            g_rvec[(((c << 8) | b8) << 4) + il] = make_float2(xr, xi);
        }
    }
}

// ---------------------------------------------------------------------------
// Main kernel. One thread per sample, balanced contiguous chunk per block.
// Table (128 KB) in smem, plain layout; column pairs read in lane-rotated
// order (deterministic 4-phase LDS.128, idx-independent). Register pair u
// of the state holds logical pair (u+rot)&7 after the first matvec.
// ---------------------------------------------------------------------------
__global__ __launch_bounds__(512) void k_main(float* __restrict__ out, int N) {
    extern __shared__ float2 sSeg[];  // 64 * 256 float2 = 128 KB

    {
        const float4* src = reinterpret_cast<const float4*>(g_seg);
        float4* dst = reinterpret_cast<float4*>(sSeg);
        for (int e = threadIdx.x; e < 64 * 128; e += blockDim.x) dst[e] = src[e];
    }
    __syncthreads();

    unsigned sb;
    asm("{ .reg .u64 t; cvta.to.shared.u64 t, %1; cvt.u32.u64 %0, t; }"
        : "=r"(sb) : "l"(sSeg));
    const unsigned rot    = threadIdx.x & 7u;
    const unsigned rot16  = rot << 4;
    const unsigned rot256 = rot << 8;

    int chunk = (N + gridDim.x - 1) / gridDim.x;
    int start = blockIdx.x * chunk;
    int end = min(start + chunk, N);

    for (int s = start + (int)threadIdx.x; s < end; s += (int)blockDim.x) {
        ull packed = __ldg(&g_xpack[s]);
        unsigned idxl = (unsigned)(packed >> 50);         // x0..x13
        unsigned idxr = (unsigned)packed & 0x3FFFu;       // x50..x63
        ull sp = packed << 14;                            // x14 at bit 63

        // ---- start vector: Lvec[idxl], logical register order ----
        float mr[16], mi[16];
        {
            const char* lb = (const char*)g_lvec + ((size_t)idxl << 7);
#pragma unroll
            for (int u = 0; u < 8; u++) {
                ull a, b;
                ldg128(lb + (u << 4), a, b);
                unpack2(a, mr[2 * u],     mi[2 * u]);
                unpack2(b, mr[2 * u + 1], mi[2 * u + 1]);
            }
        }

        // ---- matvec 1: rows addressed by immediate offsets ----
        {
            unsigned idx = (unsigned)(sp >> 58);
            sp <<= 6;
            unsigned mb = sb + (idx << 11);
            ull P[16], Q[16];
#pragma unroll
            for (int e = 0; e < 16; e++) { P[e] = 0ull; Q[e] = 0ull; }
            unsigned pu[8];
#pragma unroll
            for (int u = 0; u < 8; u++) pu[u] = mb + ((rot16 + (u << 4)) & 127u);
#pragma unroll
            for (int i = 0; i < 16; i++) {
                float ar = mr[i], ai = mi[i];
                ull arr = pack2(ar, ar), ai2 = pack2(ai, -ai);
#pragma unroll
                for (int u = 0; u < 8; u++) {
                    ull b0, b1;
                    lds128(pu[u] + (unsigned)(i << 7), b0, b1);
                    P[2 * u]     = ffma2(arr, b0, P[2 * u]);
                    Q[2 * u]     = ffma2(ai2, b0, Q[2 * u]);
                    P[2 * u + 1] = ffma2(arr, b1, P[2 * u + 1]);
                    Q[2 * u + 1] = ffma2(ai2, b1, Q[2 * u + 1]);
                }
            }
#pragma unroll
            for (int e = 0; e < 16; e++) {
                float pl, ph, ql, qh;
                unpack2(P[e], pl, ph);
                unpack2(Q[e], ql, qh);
                mr[e] = pl + qh;   // nr = ar*bx - ai*by
                mi[e] = ph + ql;   // ni = ar*by + ai*bx
            }
        }

        // ---- matvecs 2..6: state pair u holds logical pair (u+rot)&7 ----
#pragma unroll 1
        for (int kseg = 1; kseg < 6; kseg++) {
            unsigned idx = (unsigned)(sp >> 58);
            sp <<= 6;
            unsigned mb = sb + (idx << 11);
            ull P[16], Q[16];
#pragma unroll
            for (int e = 0; e < 16; e++) { P[e] = 0ull; Q[e] = 0ull; }
            unsigned pu[8];
#pragma unroll
            for (int u = 0; u < 8; u++) pu[u] = mb + ((rot16 + (u << 4)) & 127u);
#pragma unroll
            for (int spn = 0; spn < 8; spn++) {
                unsigned row = (rot256 + (unsigned)(spn << 8)) & 2047u;
#pragma unroll
                for (int hf = 0; hf < 2; hf++) {
                    float ar = mr[2 * spn + hf], ai = mi[2 * spn + hf];
                    ull arr = pack2(ar, ar), ai2 = pack2(ai, -ai);
#pragma unroll
                    for (int u = 0; u < 8; u++) {
                        ull b0, b1;
                        lds128(pu[u] + row + (unsigned)(hf << 7), b0, b1);
                        P[2 * u]     = ffma2(arr, b0, P[2 * u]);
                        Q[2 * u]     = ffma2(ai2, b0, Q[2 * u]);
                        P[2 * u + 1] = ffma2(arr, b1, P[2 * u + 1]);
                        Q[2 * u + 1] = ffma2(ai2, b1, Q[2 * u + 1]);
                    }
                }
            }
#pragma unroll
            for (int e = 0; e < 16; e++) {
                float pl, ph, ql, qh;
                unpack2(P[e], pl, ph);
                unpack2(Q[e], ql, qh);
                mr[e] = pl + qh;
                mi[e] = ph + ql;
            }
        }

        // ---- final dot with Rvec[idxr], same pair rotation ----
        float accr = 0.f, acci = 0.f;
        {
            const char* rb = (const char*)g_rvec + ((size_t)idxr << 7);
#pragma unroll
            for (int u = 0; u < 8; u++) {
                ull a, b;
                ldg128(rb + ((rot16 + (u << 4)) & 127u), a, b);
                float c0x, c0y, c1x, c1y;
                unpack2(a, c0x, c0y);
                unpack2(b, c1x, c1y);
                int e0 = 2 * u, e1 = 2 * u + 1;
                accr = fmaf(mr[e0], c0x, accr);  accr = fmaf(-mi[e0], c0y, accr);
                acci = fmaf(mr[e0], c0y, acci);  acci = fmaf(mi[e0], c0x, acci);
                accr = fmaf(mr[e1], c1x, accr);  accr = fmaf(-mi[e1], c1y, accr);
                acci = fmaf(mr[e1], c1y, acci);  acci = fmaf(mi[e1], c1x, acci);
            }
        }

        out[s]     = accr;
        out[N + s] = acci;
    }
}

// ---------------------------------------------------------------------------
// kernel_launch
// inputs (metadata order): x, left_r, left_i, bulk_r, bulk_i, right_r, right_i
// out: float32, [2, N] flattened (re then im)
// ---------------------------------------------------------------------------
extern "C" void kernel_launch(void* const* d_in, const int* in_sizes, int n_in,
                              void* d_out, int out_size) {
    const int*   x       = (const int*)d_in[0];
    const float* left_r  = (const float*)d_in[1];
    const float* left_i  = (const float*)d_in[2];
    const float* bulk_r  = (const float*)d_in[3];
    const float* bulk_i  = (const float*)d_in[4];
    const float* right_r = (const float*)d_in[5];
    const float* right_i = (const float*)d_in[6];
    float* out = (float*)d_out;

    int N = in_sizes[0] / 64;

    static const size_t kSmem = 64 * 256 * sizeof(float2);  // 128 KB
    cudaFuncSetAttribute(k_main, cudaFuncAttributeMaxDynamicSharedMemorySize,
                         (int)kSmem);

    // Each 256-thread block = 8 warps, each warp packs 32 samples -> 256/block.
    k0_pack<<<(N + 255) / 256, 256>>>(x, N);
    k1_seed<<<1, 512>>>(bulk_r, bulk_i, left_r, left_i, right_r, right_i);
    k2_seg6<<<64, 256>>>();
    k3_mid<<<32, 256>>>();
    k4_big<<<128, 256>>>();
    k_main<<<148, 512, kSmem>>>(out, N);
}